// round 7
// baseline (speedup 1.0000x reference)
#include <cuda_runtime.h>
#include <math.h>

#define NB 64
#define TT 1024
#define DD 512
#define HH 512
#define FH 2048    // 4*H
#define GRID_R 128 // recurrence blocks (1/SM, all co-resident)
#define NTHR 512   // threads per recurrence block (16 warps)
#define HS_STRIDE 68

// Scratch: xw in [T, N, 4H] layout (512 MB), TRANSPOSED ping-pong h, barrier.
__device__ float g_xw[(size_t)NB * TT * FH];
__device__ float g_hT[2][HH * NB];     // [buf][k][n]
__device__ unsigned g_bar;

union F2 { float2 f; unsigned long long u; };

#define FMA2(d, a, b) \
    asm("fma.rn.f32x2 %0, %1, %2, %3;" : "=l"((d).u) : "l"((a).u), "l"((b).u), "l"((d).u))

__device__ __forceinline__ float tanh_fast(float x) {
    float y;
    asm("tanh.approx.f32 %0, %1;" : "=f"(y) : "f"(x));
    return y;
}
__device__ __forceinline__ float sigmoid_fast(float x) {
    return fmaf(tanh_fast(0.5f * x), 0.5f, 0.5f);
}

// ---------------------------------------------------------------------------
// Transpose h0 [64][512] -> g_hT[1][k][n] (one-off, 128KB)
// ---------------------------------------------------------------------------
__global__ __launch_bounds__(256) void transpose_h0_kernel(const float* __restrict__ h0)
{
    int idx = blockIdx.x * 256 + threadIdx.x;   // 0..32767
    int n = idx >> 9;
    int k = idx & 511;
    g_hT[1][k * NB + n] = h0[idx];
}

// ---------------------------------------------------------------------------
// Phase 1: xw[t*64+n, j] = sum_k x[n*1024+t, k] * Wx[k, j] + b[j]
// fp32 SGEMM with packed f32x2 FMA: BM=128, BN=128, BK=8, 256 thr, 8x8/thr.
// Output rows written TRANSPOSED to [T, N] order for phase-2 locality.
// ---------------------------------------------------------------------------
__global__ __launch_bounds__(256) void sgemm_xw_kernel(
    const float* __restrict__ A,      // x    [65536, 512]
    const float* __restrict__ B,      // Wx   [512, 2048]
    const float* __restrict__ bias)   // b    [2048]
{
    __shared__ float As[8][128];
    __shared__ float Bs2[8][256];     // duplicated pairs (v, v)

    const int tid = threadIdx.x;
    const int bx = blockIdx.x;    // col block (0..15)
    const int by = blockIdx.y;    // row block (0..511)
    const int tx = tid & 15;
    const int ty = tid >> 4;

    if (bx == 0 && by == 0 && tid == 0) g_bar = 0u;   // barrier reset for phase 2

    const float* Ab = A + (size_t)by * 128 * DD;
    const float* Bb = B + bx * 128;

    F2 acc[4][8];                 // [row-pair][col]
    #pragma unroll
    for (int i = 0; i < 4; ++i)
        #pragma unroll
        for (int j = 0; j < 8; ++j)
            acc[i][j].u = 0ull;

    const int arow = tid >> 1;          // 0..127
    const int ac4  = (tid & 1) * 4;     // 0 or 4
    const int brow = tid >> 5;          // 0..7
    const int bc4  = (tid & 31) * 4;    // 0..124

    for (int kc = 0; kc < DD; kc += 8) {
        float4 av = *(const float4*)(Ab + (size_t)arow * DD + kc + ac4);
        float4 bv = *(const float4*)(Bb + (size_t)(kc + brow) * FH + bc4);
        As[ac4 + 0][arow] = av.x;
        As[ac4 + 1][arow] = av.y;
        As[ac4 + 2][arow] = av.z;
        As[ac4 + 3][arow] = av.w;
        *(float2*)&Bs2[brow][2 * (bc4 + 0)] = make_float2(bv.x, bv.x);
        *(float2*)&Bs2[brow][2 * (bc4 + 1)] = make_float2(bv.y, bv.y);
        *(float2*)&Bs2[brow][2 * (bc4 + 2)] = make_float2(bv.z, bv.z);
        *(float2*)&Bs2[brow][2 * (bc4 + 3)] = make_float2(bv.w, bv.w);
        __syncthreads();

        #pragma unroll
        for (int k = 0; k < 8; ++k) {
            float4 a0 = *(const float4*)&As[k][ty * 8];
            float4 a1 = *(const float4*)&As[k][ty * 8 + 4];
            F2 ra[4];
            ra[0].f = make_float2(a0.x, a0.y);
            ra[1].f = make_float2(a0.z, a0.w);
            ra[2].f = make_float2(a1.x, a1.y);
            ra[3].f = make_float2(a1.z, a1.w);
            #pragma unroll
            for (int j = 0; j < 8; ++j) {
                F2 rb = *(F2*)&Bs2[k][2 * (tx * 8 + j)];
                #pragma unroll
                for (int i = 0; i < 4; ++i)
                    FMA2(acc[i][j], ra[i], rb);
            }
        }
        __syncthreads();
    }

    float bb[8];
    #pragma unroll
    for (int j = 0; j < 8; ++j)
        bb[j] = bias[bx * 128 + tx * 8 + j];

    #pragma unroll
    for (int i = 0; i < 4; ++i) {
        #pragma unroll
        for (int half = 0; half < 2; ++half) {
            int r = by * 128 + ty * 8 + i * 2 + half;   // global A row
            int n = r >> 10;                            // batch
            int t = r & 1023;                           // time
            float* C = g_xw + (size_t)(t * NB + n) * FH + bx * 128;
            float4 v0, v1;
            v0.x = (half ? acc[i][0].f.y : acc[i][0].f.x) + bb[0];
            v0.y = (half ? acc[i][1].f.y : acc[i][1].f.x) + bb[1];
            v0.z = (half ? acc[i][2].f.y : acc[i][2].f.x) + bb[2];
            v0.w = (half ? acc[i][3].f.y : acc[i][3].f.x) + bb[3];
            v1.x = (half ? acc[i][4].f.y : acc[i][4].f.x) + bb[4];
            v1.y = (half ? acc[i][5].f.y : acc[i][5].f.x) + bb[5];
            v1.z = (half ? acc[i][6].f.y : acc[i][6].f.x) + bb[6];
            v1.w = (half ? acc[i][7].f.y : acc[i][7].f.x) + bb[7];
            *(float4*)(C + tx * 8)     = v0;
            *(float4*)(C + tx * 8 + 4) = v1;
        }
    }
}

// ---------------------------------------------------------------------------
// Phase 2: ONE persistent kernel, software grid barrier between timesteps.
// 128 blocks x 512 threads. Block b owns 4 hidden units (m0 = b*4) -> 16 cols.
// Whs2 [512 x 16] duplicated pairs (64 KB, loaded once).
// Hs   [512 x 68] h staging (136 KB) -- h comes pre-transposed from g_hT, so
// staging is straight LDG.128 -> STS.128, and the GEMM LDS reads are
// conflict-free per-phase without any swizzle. Ap (reduce) ALIASES Hs.
// Barrier overlap: store g_hT -> fence -> arrive -> (out store + next-xw
// prefetch run during the spin) -> wait -> next step.
// ---------------------------------------------------------------------------
__global__ __launch_bounds__(NTHR) void lstm_persist_kernel(
    const float* __restrict__ Wh,     // [512, 2048]
    float* __restrict__ out)          // [64, 1024, 512]
{
    extern __shared__ char sm_raw[];
    float2* Whs2 = (float2*)sm_raw;                       // [512*16] pairs, 64KB
    float*  Hs   = (float*)(sm_raw + 65536);              // [512][68], 136KB
    float*  Ap   = Hs;                                    // aliased reduce buf

    const int tid  = threadIdx.x;
    const int w    = tid >> 5;
    const int lane = tid & 31;
    const int ln   = lane >> 2;   // 0..7  -> n group (8 batches)
    const int lc   = lane & 3;    // 0..3  -> c group (4 cols)
    const int m0   = blockIdx.x * 4;

    // Load Wh slice once, duplicated: col c = g*4+u -> global g*512 + m0 + u
    {
        const int wc  = tid & 15;
        const int wk0 = tid >> 4;       // 0..31
        const int wcol = (wc >> 2) * HH + m0 + (wc & 3);
        #pragma unroll 4
        for (int j = 0; j < 16; ++j) {
            int k = wk0 + 32 * j;
            float v = Wh[(size_t)k * FH + wcol];
            Whs2[k * 16 + wc] = make_float2(v, v);
        }
    }

    const int en = (tid >> 2) & 63;   // epilogue batch 0..63 (tid<256 active)
    const int eu = tid & 3;           // epilogue unit  0..3
    float creg = 0.f;

    // Staging map: thread -> row sk(+128j), float4 f = sq + 4m (64B groups)
    const int sk = tid >> 2;      // 0..127
    const int sq = tid & 3;       // 0..3

    // Prefetch xw for t = 0
    float xwv[4];
    #pragma unroll
    for (int g = 0; g < 4; ++g)
        xwv[g] = g_xw[(size_t)(0 * NB + en) * FH + g * HH + m0 + eu];

    for (int t = 0; t < TT; ++t) {
        const float* hp = g_hT[(t + 1) & 1];   // (t-1) mod 2; t=0 -> h0T in buf 1

        // Stage h_{t-1} -> Hs (already transposed in global; straight copy)
        #pragma unroll
        for (int j = 0; j < 4; ++j) {
            int row = sk + 128 * j;
            const float4* src = (const float4*)(hp + row * NB);
            float4* dst = (float4*)(Hs + row * HS_STRIDE);
            #pragma unroll
            for (int m = 0; m < 4; ++m) {
                int f = sq + 4 * m;
                dst[f] = __ldcg(src + f);
            }
        }
        __syncthreads();

        // Split-K: warp w owns k in [w*32, w*32+32). Lane tile 8n x 4c,
        // n packed into 4 f32x2 pairs; Wh operand pre-duplicated pairs.
        F2 acc[4][4];
        #pragma unroll
        for (int p = 0; p < 4; ++p)
            #pragma unroll
            for (int j = 0; j < 4; ++j)
                acc[p][j].u = 0ull;

        #pragma unroll 4
        for (int kk = 0; kk < 32; ++kk) {
            int k = w * 32 + kk;
            const float* hrow = &Hs[k * HS_STRIDE];
            float4 ha = *(const float4*)&hrow[ln * 8];
            float4 hb = *(const float4*)&hrow[ln * 8 + 4];
            F2 hv[4];
            hv[0].f = make_float2(ha.x, ha.y);
            hv[1].f = make_float2(ha.z, ha.w);
            hv[2].f = make_float2(hb.x, hb.y);
            hv[3].f = make_float2(hb.z, hb.w);
            const float4* wp = (const float4*)&Whs2[k * 16 + lc * 4];
            float4 w0 = wp[0];                      // (c0,c0,c1,c1)
            float4 w1 = wp[1];                      // (c2,c2,c3,c3)
            F2 wv[4];
            wv[0].f = make_float2(w0.x, w0.y);
            wv[1].f = make_float2(w0.z, w0.w);
            wv[2].f = make_float2(w1.x, w1.y);
            wv[3].f = make_float2(w1.z, w1.w);
            #pragma unroll
            for (int j = 0; j < 4; ++j)
                #pragma unroll
                for (int p = 0; p < 4; ++p)
                    FMA2(acc[p][j], hv[p], wv[j]);
        }

        __syncthreads();   // all warps done READING Hs; safe to alias as Ap

        // Cross-warp partials (stride 66, float2 stores)
        #pragma unroll
        for (int p = 0; p < 4; ++p)
            #pragma unroll
            for (int j = 0; j < 4; ++j)
                *(float2*)&Ap[(w * 16 + lc * 4 + j) * 66 + ln * 8 + 2 * p] =
                    acc[p][j].f;
        __syncthreads();

        float hval = 0.f;
        if (tid < 256) {
            float a[4];
            #pragma unroll
            for (int g = 0; g < 4; ++g) {
                float s = xwv[g];
                #pragma unroll
                for (int ww = 0; ww < 16; ++ww)
                    s += Ap[(ww * 16 + g * 4 + eu) * 66 + en];
                a[g] = s;
            }
            float ig = sigmoid_fast(a[0]);
            float fg = sigmoid_fast(a[1]);
            float og = sigmoid_fast(a[2]);
            float gg = tanh_fast(a[3]);
            creg = fmaf(fg, creg, ig * gg);
            hval = og * tanh_fast(creg);
            // h for next step FIRST (it's what other blocks wait on)
            g_hT[t & 1][(m0 + eu) * NB + en] = hval;
        }

        if (t + 1 < TT) {
            __threadfence();          // release h stores
            __syncthreads();
            if (tid == 0)
                atomicAdd(&g_bar, 1u);
            // ---- overlapped with the spin: out store + next xw prefetch ----
            if (tid < 256) {
                out[(size_t)en * TT * HH + (size_t)t * HH + m0 + eu] = hval;
                #pragma unroll
                for (int g = 0; g < 4; ++g)
                    xwv[g] = g_xw[(size_t)((t + 1) * NB + en) * FH + g * HH + m0 + eu];
            }
            if (tid == 0) {
                const unsigned target = (unsigned)(t + 1) * GRID_R;
                while (*((volatile unsigned*)&g_bar) < target) { }
                __threadfence();      // acquire
            }
            __syncthreads();
        } else {
            if (tid < 256)
                out[(size_t)en * TT * HH + (size_t)t * HH + m0 + eu] = hval;
        }
    }
}

// ---------------------------------------------------------------------------
extern "C" void kernel_launch(void* const* d_in, const int* in_sizes, int n_in,
                              void* d_out, int out_size)
{
    const float* x  = (const float*)d_in[0];   // [64, 1024, 512]
    const float* h0 = (const float*)d_in[1];   // [64, 512]
    const float* Wx = (const float*)d_in[2];   // [512, 2048]
    const float* Wh = (const float*)d_in[3];   // [512, 2048]
    const float* b  = (const float*)d_in[4];   // [2048]
    float* out = (float*)d_out;                // [64, 1024, 512]

    const int smem_bytes = 65536 + DD * HS_STRIDE * 4;   // 64KB + 136KB = 200KB
    cudaFuncSetAttribute(lstm_persist_kernel,
                         cudaFuncAttributeMaxDynamicSharedMemorySize, smem_bytes);

    transpose_h0_kernel<<<128, 256>>>(h0);

    dim3 g1(FH / 128, (NB * TT) / 128);        // (16, 512)
    sgemm_xw_kernel<<<g1, 256>>>(x, Wx, b);

    lstm_persist_kernel<<<GRID_R, NTHR, smem_bytes>>>(Wh, out);
}